// round 2
// baseline (speedup 1.0000x reference)
#include <cuda_runtime.h>

// IDWT (inverse Haar) — pure streaming kernel.
// Inputs: LL, LH, HL, HH each [B=16, C=64, H2=128, W2=128] fp32.
// Output: [16, 64, 256, 256] fp32.
// out[2i,2j]=a, out[2i,2j+1]=b, out[2i+1,2j]=c, out[2i+1,2j+1]=d where
//   a=(LL+LH+HL+HH)/2, b=(LL+LH-HL-HH)/2, c=(LL-LH+HL-HH)/2, d=(LL-LH-HL+HH)/2

static constexpr int W2 = 128;            // input width
static constexpr int H2 = 128;            // input height
static constexpr int W4 = W2 / 4;         // float4 groups per input row = 32
static constexpr int OUT_ROW_F4 = (2 * W2) / 4;  // 64 float4 per output row

__global__ void __launch_bounds__(256) idwt_haar_kernel(
    const float4* __restrict__ ll4,
    const float4* __restrict__ lh4,
    const float4* __restrict__ hl4,
    const float4* __restrict__ hh4,
    float4* __restrict__ out4)
{
    unsigned idx = blockIdx.x * blockDim.x + threadIdx.x;  // one per 4 input coeffs

    float4 ll = ll4[idx];
    float4 lh = lh4[idx];
    float4 hl = hl4[idx];
    float4 hh = hh4[idx];

    // Per-lane butterflies
    float4 a, b, c, d;
    {
        float s0, s1, d0, d1;
        s0 = ll.x + lh.x; s1 = hl.x + hh.x; d0 = ll.x - lh.x; d1 = hl.x - hh.x;
        a.x = 0.5f * (s0 + s1); b.x = 0.5f * (s0 - s1);
        c.x = 0.5f * (d0 + d1); d.x = 0.5f * (d0 - d1);
        s0 = ll.y + lh.y; s1 = hl.y + hh.y; d0 = ll.y - lh.y; d1 = hl.y - hh.y;
        a.y = 0.5f * (s0 + s1); b.y = 0.5f * (s0 - s1);
        c.y = 0.5f * (d0 + d1); d.y = 0.5f * (d0 - d1);
        s0 = ll.z + lh.z; s1 = hl.z + hh.z; d0 = ll.z - lh.z; d1 = hl.z - hh.z;
        a.z = 0.5f * (s0 + s1); b.z = 0.5f * (s0 - s1);
        c.z = 0.5f * (d0 + d1); d.z = 0.5f * (d0 - d1);
        s0 = ll.w + lh.w; s1 = hl.w + hh.w; d0 = ll.w - lh.w; d1 = hl.w - hh.w;
        a.w = 0.5f * (s0 + s1); b.w = 0.5f * (s0 - s1);
        c.w = 0.5f * (d0 + d1); d.w = 0.5f * (d0 - d1);
    }

    // idx = plane*4096 + row*32 + col4 (plane in [0,1024), row in [0,128), col4 in [0,32)).
    // Output base (float4 units) = plane*32768 + (2*row)*64 + col4*2
    //                            = 2*idx + (idx & ~31u)*2*... rewritten:
    //   plane*32768 + row*8192... simpler: base = 2*idx + 2*row*OUT_ROW_F4 - 2*row*W4... keep explicit:
    unsigned col4  = idx & (W4 - 1);          // 0..31
    unsigned row   = (idx >> 5) & (H2 - 1);   // 0..127
    unsigned plane = idx >> 12;               // 0..1023

    // Max base = 1023*32768 + 254*64 + 62 < 2^26 → fits 32-bit.
    unsigned base = plane * (2u * H2 * OUT_ROW_F4)
                  + (2u * row) * OUT_ROW_F4
                  + col4 * 2u;

    // Row 2i: interleave a,b
    out4[base + 0] = make_float4(a.x, b.x, a.y, b.y);
    out4[base + 1] = make_float4(a.z, b.z, a.w, b.w);
    // Row 2i+1: interleave c,d
    out4[base + OUT_ROW_F4 + 0] = make_float4(c.x, d.x, c.y, d.y);
    out4[base + OUT_ROW_F4 + 1] = make_float4(c.z, d.z, c.w, d.w);
}

extern "C" void kernel_launch(void* const* d_in, const int* in_sizes, int n_in,
                              void* d_out, int out_size)
{
    const float4* ll = (const float4*)d_in[0];
    const float4* lh = (const float4*)d_in[1];
    const float4* hl = (const float4*)d_in[2];
    const float4* hh = (const float4*)d_in[3];
    float4* out = (float4*)d_out;

    int n_groups = in_sizes[0] / 4;              // 2^22
    int block = 256;
    int grid = (n_groups + block - 1) / block;   // 16384
    idwt_haar_kernel<<<grid, block>>>(ll, lh, hl, hh, out);
}